// round 14
// baseline (speedup 1.0000x reference)
#include <cuda_runtime.h>
#include <math.h>

typedef unsigned long long u64;

#define KK 19
#define KP 20

// ---- constant-bank layout (floats) ----
#define CW1   0      // 1024 [d*32+c]  select_w1 * bn_scale
#define CM2   1024   // 128  [d*4+j]   rsC*wq@[sK0,sK1,sK2,bk]
#define CSP   1152   // 80   [j*20+k]  rows 0..2: sV_j@Wo2 ; row 3: bv@Wo2 + bo@WoT2
#define CSC2  1232   // 4    cM2
#define CB1F  1236   // 32   folded BN bias
#define CW2   1268   // 32   select_w2
#define CB2   1300   // 1 (+3 pad)
#define CSG   1304   // 400  [k'*20+k] G = BV@Wo2
#define CSC1  1704   // 20   cM1 (pad k=19 -> 0)
#define CBOUT 1724   // 20   b_out + bt@w_out (pad k=19 -> 0)
#define CSZ   1744

// ---- global weight buffer (smem-side): M1 then WT1 ----
#define GM1   0      // 640 [d*20+k] M1 = rsC*wq@BK^T
#define GWT1  640    // 640 [d*20+k] WT1 = wt[:32]@w_out
#define BUF2_SZ 1280

__constant__ __align__(16) float c_w[CSZ];
__device__ __align__(16) float g_cw[CSZ];
__device__ __align__(16) float g_buf[BUF2_SZ];

__device__ __forceinline__ u64 ffma2(u64 a, u64 b, u64 c) {
    u64 d; asm("fma.rn.f32x2 %0, %1, %2, %3;" : "=l"(d) : "l"(a), "l"(b), "l"(c)); return d;
}
__device__ __forceinline__ u64 pack2(float x, float y) {
    u64 r; asm("mov.b64 %0, {%1, %2};" : "=l"(r) : "f"(x), "f"(y)); return r;
}
__device__ __forceinline__ void unpack2(u64 v, float& x, float& y) {
    asm("mov.b64 {%0, %1}, %2;" : "=f"(x), "=f"(y) : "l"(v));
}
__device__ __forceinline__ void cld4(int idx, u64& a, u64& b) {
    float4 v = *reinterpret_cast<const float4*>(&c_w[idx]);
    a = pack2(v.x, v.y); b = pack2(v.z, v.w);
}
__device__ __forceinline__ u64 cld2(int idx) {
    float2 v = *reinterpret_cast<const float2*>(&c_w[idx]);
    return pack2(v.x, v.y);
}

// ============================================================================
// Setup kernel: fold all weights. 1 block, 1024 threads. (verified R11)
// ============================================================================
__global__ void setup_kernel(
    const float* __restrict__ z, const float* __restrict__ select_w1,
    const float* __restrict__ bn_gamma, const float* __restrict__ bn_beta,
    const float* __restrict__ bn_mean, const float* __restrict__ bn_var,
    const float* __restrict__ select_w2, const float* __restrict__ select_b2,
    const float* __restrict__ wq, const float* __restrict__ bq,
    const float* __restrict__ wk, const float* __restrict__ bk,
    const float* __restrict__ wv, const float* __restrict__ bv,
    const float* __restrict__ wo, const float* __restrict__ bo,
    const float* __restrict__ wt, const float* __restrict__ bt,
    const float* __restrict__ w_out, const float* __restrict__ b_out,
    const float* __restrict__ w_gen, const float* __restrict__ b_gen)
{
    __shared__ float s_zw[32];
    __shared__ float s_sK[96], s_sV[96];
    __shared__ float s_WoT2[640], s_Wo2[640];
    __shared__ float s_base[608];
    __shared__ float s_BK[608], s_BV[608];
    __shared__ float s_wq[1024], s_wk[1024], s_wv[1024], s_wo[1024];
    __shared__ float s_wt[2048], s_wout[608], s_wgen[1216];
    const int t = threadIdx.x;
    const float rsC = 0.17677669529663687f;

    // ---- burst prefetch (independent LDGs, MLP-overlapped) ----
    s_wq[t] = wq[t];
    s_wk[t] = wk[t];
    s_wv[t] = wv[t];
    s_wo[t] = wo[t];
    s_wt[t] = wt[t];
    s_wt[1024 + t] = wt[1024 + t];
    if (t < 608)  s_wout[t] = w_out[t];
    s_wgen[t] = (t < 1216) ? w_gen[t] : 0.f;
    if (t < 192)  s_wgen[1024 + t] = w_gen[1024 + t];

    {
        int c = t & 31;
        float sc = bn_gamma[c] * rsqrtf(bn_var[c] + 1e-4f);
        g_cw[CW1 + t] = select_w1[t] * sc;
    }
    if (t < 32) {
        float sc = bn_gamma[t] * rsqrtf(bn_var[t] + 1e-4f);
        g_cw[CB1F + t] = bn_beta[t] - bn_mean[t] * sc;
        g_cw[CW2 + t]  = select_w2[t];
    }
    if (t == 32) g_cw[CB2] = select_b2[0];
    __syncthreads();

    // -------- Stage A --------
    if (t < 32) {
        float acc = b_gen[t];
        #pragma unroll
        for (int i = 0; i < 16; ++i) acc += z[i] * s_wgen[i * 32 + t];
        s_zw[t] = acc;
    }
    if (t < 96) {
        int j = t / 32, c = t % 32;
        float aK = 0.f, aV = 0.f;
        #pragma unroll
        for (int d = 0; d < 32; ++d) {
            float w = s_wgen[(35 + j) * 32 + d];
            aK += w * s_wk[d * 32 + c];
            aV += w * s_wv[d * 32 + c];
        }
        s_sK[t] = aK; s_sV[t] = aV;
    }
    if (t < 640) {
        int d = t / KP, k = t % KP;
        float a1 = 0.f, a2w = 0.f;
        if (k < KK) {
            #pragma unroll
            for (int e = 0; e < 32; ++e) {
                a1  += s_wt[d * 32 + e]        * s_wout[e * KK + k];
                a2w += s_wt[(32 + d) * 32 + e] * s_wout[e * KK + k];
            }
        }
        g_buf[GWT1 + d * KP + k] = a1;
        s_WoT2[t] = a2w;
    }
    if (t >= 640 && t < 660) {
        int k = t - 640; float a = 0.f;
        if (k < KK) {
            a = b_out[k];
            #pragma unroll
            for (int e = 0; e < 32; ++e) a += bt[e] * s_wout[e * KK + k];
        }
        g_cw[CBOUT + k] = a;
    }
    __syncthreads();

    // -------- Stage B --------
    if (t < 608)
        s_base[t] = s_zw[t & 31] + s_wgen[(16 + (t >> 5)) * 32 + (t & 31)];
    if (t < 640) {
        int c = t / KP, k = t % KP; float a = 0.f;
        if (k < KK) {
            #pragma unroll
            for (int d = 0; d < 32; ++d) a += s_wo[c * 32 + d] * s_WoT2[d * KP + k];
        }
        s_Wo2[t] = a;
    }
    __syncthreads();

    // -------- Stage C --------
    if (t < 608) {
        int k = t >> 5, c = t & 31;
        float ak = 0.f, av = 0.f;
        #pragma unroll
        for (int d = 0; d < 32; ++d) {
            float b = s_base[k * 32 + d];
            ak += b * s_wk[d * 32 + c];
            av += b * s_wv[d * 32 + c];
        }
        s_BK[t] = ak; s_BV[t] = av;
    }
    if (t >= 608 && t < 688) {
        int j = (t - 608) / KP, k = (t - 608) % KP;
        float a = 0.f;
        if (k < KK) {
            if (j < 3) {
                #pragma unroll
                for (int c = 0; c < 32; ++c) a += s_sV[j * 32 + c] * s_Wo2[c * KP + k];
            } else {
                #pragma unroll
                for (int c = 0; c < 32; ++c) a += bv[c] * s_Wo2[c * KP + k];
                #pragma unroll
                for (int d = 0; d < 32; ++d) a += bo[d] * s_WoT2[d * KP + k];
            }
        }
        g_cw[CSP + j * KP + k] = a;
    }
    __syncthreads();

    // -------- Stage D --------
    if (t < 640) {   // M1
        int d = t / KP, k = t % KP; float a = 0.f;
        if (k < KK) {
            #pragma unroll
            for (int c = 0; c < 32; ++c) a += s_wq[d * 32 + c] * s_BK[k * 32 + c];
        }
        g_buf[GM1 + d * KP + k] = a * rsC;
    } else if (t < 768) {   // M2
        int d = (t - 640) / 4, j = (t - 640) % 4; float a = 0.f;
        if (j < 3) {
            #pragma unroll
            for (int c = 0; c < 32; ++c) a += s_wq[d * 32 + c] * s_sK[j * 32 + c];
        } else {
            #pragma unroll
            for (int c = 0; c < 32; ++c) a += s_wq[d * 32 + c] * bk[c];
        }
        g_cw[CM2 + d * 4 + j] = a * rsC;
    } else if (t < 788) {   // cM1
        int k = t - 768; float a = 0.f;
        if (k < KK) {
            #pragma unroll
            for (int c = 0; c < 32; ++c) a += bq[c] * s_BK[k * 32 + c];
        }
        g_cw[CSC1 + k] = a * rsC;
    } else if (t < 792) {   // cM2
        int j = t - 788; float a = 0.f;
        if (j < 3) {
            #pragma unroll
            for (int c = 0; c < 32; ++c) a += bq[c] * s_sK[j * 32 + c];
        } else {
            #pragma unroll
            for (int c = 0; c < 32; ++c) a += bq[c] * bk[c];
        }
        g_cw[CSC2 + j] = a * rsC;
    } else {                // SG
        for (int u = t - 792; u < KK * KP; u += 232) {
            int kp = u / KP, k = u % KP; float a = 0.f;
            if (k < KK) {
                #pragma unroll
                for (int c = 0; c < 32; ++c) a += s_BV[kp * 32 + c] * s_Wo2[c * KP + k];
            }
            g_cw[CSG + kp * KP + k] = a;
        }
    }
}

// ============================================================================
// Attention-logit chunk: cols [C0, C0+4*NW). IN-PLACE: cp[k] <- exp(lg)*cp[k].
// ============================================================================
template<int C0, int NW>
__device__ __forceinline__ void t_chunk1(
    const float* sM1, const float* f, float* cp,
    float qsK, float qbk, float& Se, float& Sm)
{
    u64 T[2 * NW];
    #pragma unroll
    for (int i = 0; i < 2 * NW; ++i) T[i] = cld2(CSC1 + C0 + 2 * i);
    #pragma unroll
    for (int d = 0; d < 32; ++d) {
        const ulonglong2* r = reinterpret_cast<const ulonglong2*>(sM1 + d * KP + C0);
        u64 fd2 = pack2(f[d], f[d]);
        #pragma unroll
        for (int i = 0; i < NW; ++i) {
            ulonglong2 ww = r[i];
            T[2 * i]     = ffma2(ww.x, fd2, T[2 * i]);
            T[2 * i + 1] = ffma2(ww.y, fd2, T[2 * i + 1]);
        }
    }
    #pragma unroll
    for (int i = 0; i < 2 * NW; ++i) {
        const int k0 = C0 + 2 * i, k1 = k0 + 1;
        float tx, ty;
        unpack2(T[i], tx, ty);
        if (k0 < KK) { float el = __expf(fmaf(cp[k0], tx + qsK, qbk)); Se += el; cp[k0] *= el; Sm += cp[k0]; }
        if (k1 < KK) { float el = __expf(fmaf(cp[k1], ty + qsK, qbk)); Se += el; cp[k1] *= el; Sm += cp[k1]; }
    }
}

// ============================================================================
// Main kernel: 1 pt/thread; occupancy-6 / 84-reg scheduling experiment.
// ============================================================================
__global__ void __launch_bounds__(128, 6) refine_kernel(
    const float* __restrict__ feat,
    const float* __restrict__ sflow,
    const float* __restrict__ cpred,
    float* __restrict__ out,
    int N)
{
    __shared__ __align__(16) float sW[BUF2_SZ];   // M1 @0, WT1 @640
    __shared__ float sF[128 * 33];                 // feat rows, pad 33
    __shared__ float sCP[128 * KK];                // cpred rows / out rows
    const int t = threadIdx.x;
    const int nb = blockIdx.x;
    const bool full = ((nb + 1) * 128 <= N);

    // ---- weights (M1 + WT1) ----
    #pragma unroll
    for (int i = 0; i < 3; ++i) {
        int idx = t + 128 * i;
        if (idx < BUF2_SZ / 4)
            reinterpret_cast<float4*>(sW)[idx] = reinterpret_cast<const float4*>(g_buf)[idx];
    }

    // ---- staging ----
    if (full) {
        const float4* fp4 = reinterpret_cast<const float4*>(feat) + (size_t)nb * 1024;
        #pragma unroll
        for (int i = 0; i < 8; ++i) {
            int l4 = t + 128 * i;
            float4 v = fp4[l4];
            int nl = l4 >> 3, d4 = l4 & 7;
            float* p = sF + nl * 33 + 4 * d4;
            p[0] = v.x; p[1] = v.y; p[2] = v.z; p[3] = v.w;
        }
        const float* cpg = cpred + (size_t)nb * (128 * KK);
        #pragma unroll
        for (int i = 0; i < KK; ++i) {
            int j = t + 128 * i;
            sCP[j] = cpg[j];
        }
    } else {
        const size_t base4 = (size_t)nb * 1024;
        const size_t tot4 = ((size_t)N * 32) >> 2;
        #pragma unroll
        for (int i = 0; i < 8; ++i) {
            size_t j4 = base4 + t + 128 * i;
            if (j4 < tot4) {
                float4 v = reinterpret_cast<const float4*>(feat)[j4];
                int l4 = t + 128 * i;
                int nl = l4 >> 3, d4 = l4 & 7;
                float* p = sF + nl * 33 + 4 * d4;
                p[0] = v.x; p[1] = v.y; p[2] = v.z; p[3] = v.w;
            }
        }
        const size_t baseE = (size_t)nb * (128 * KK);
        const size_t totE = (size_t)N * KK;
        #pragma unroll
        for (int i = 0; i < KK; ++i) {
            size_t gidx = baseE + t + 128 * i;
            if (gidx < totE) sCP[t + 128 * i] = cpred[gidx];
        }
    }
    __syncthreads();

    const int n = nb * 128 + t;
    if (n < N) {
        const float* sfp = sflow + (size_t)n * 3;
        const float s0 = sfp[0], s1 = sfp[1], s2v = sfp[2];

        // ---- f from own smem row ----
        float f[32];
        #pragma unroll
        for (int d = 0; d < 32; ++d) f[d] = sF[t * 33 + d];

        // ---- selection score via CONSTANT port (two halves) ----
        float vf;
        {
            float slin = c_w[CB2];
            #pragma unroll
            for (int half = 0; half < 2; ++half) {
                u64 h[8];
                #pragma unroll
                for (int i = 0; i < 8; ++i) h[i] = 0ull;
                #pragma unroll
                for (int d = 0; d < 32; ++d) {
                    u64 fd2 = pack2(f[d], f[d]);
                    #pragma unroll
                    for (int i = 0; i < 4; ++i) {
                        u64 wa, wb;
                        cld4(CW1 + d * 32 + half * 16 + 4 * i, wa, wb);
                        h[2 * i]     = ffma2(wa, fd2, h[2 * i]);
                        h[2 * i + 1] = ffma2(wb, fd2, h[2 * i + 1]);
                    }
                }
                #pragma unroll
                for (int i = 0; i < 8; ++i) {
                    const int c = half * 16 + 2 * i;
                    float x, y;
                    unpack2(h[i], x, y);
                    slin += fmaxf(x + c_w[CB1F + c], 0.f) * c_w[CW2 + c]
                          + fmaxf(y + c_w[CB1F + c + 1], 0.f) * c_w[CW2 + c + 1];
                }
            }
            const float thr = 1.3862943611198906f;   // ln(4): sigmoid(s)<0.8 <=> s<ln4
            bool tmask = (s0 != 0.f) || (s1 != 0.f) || (s2v != 0.f);
            vf = (slin < thr && tmask) ? 1.f : 0.f;
        }

        // ---- u-cols via CONSTANT port ----
        float qsK, qbk;
        {
            u64 u0 = cld2(CSC2), u1 = cld2(CSC2 + 2);
            #pragma unroll
            for (int d = 0; d < 32; ++d) {
                u64 wa, wb;
                cld4(CM2 + d * 4, wa, wb);
                u64 fd2 = pack2(f[d], f[d]);
                u0 = ffma2(wa, fd2, u0);
                u1 = ffma2(wb, fd2, u1);
            }
            float a, b, c, d2;
            unpack2(u0, a, b); unpack2(u1, c, d2);
            qsK = fmaf(s0, a, fmaf(s1, b, s2v * c));
            qbk = d2;
        }

        // ---- coarse_pred softmax (own row, stride-19 conflict-free) ----
        float cp[KK];
        {
            float S = 0.f;
            #pragma unroll
            for (int k = 0; k < KK; ++k) { cp[k] = __expf(sCP[t * KK + k]); S += cp[k]; }
            float inv = 1.f / S;
            #pragma unroll
            for (int k = 0; k < KK; ++k) cp[k] *= inv;
        }

        // ---- attention logits (smem M1 + const cM1), chunked ----
        float Se = 0.f, Sm = 0.f;
        t_chunk1<0, 2>(sW + GM1, f, cp, qsK, qbk, Se, Sm);
        t_chunk1<8, 2>(sW + GM1, f, cp, qsK, qbk, Se, Sm);
        t_chunk1<16, 1>(sW + GM1, f, cp, qsK, qbk, Se, Sm);
        // f register live range ends here

        const float inv = 1.f / Se;
        const float g = vf * inv;
        const float s2 = Sm * inv;

        // ================= PHASE B: output accumulation ==================
        u64 O[10];
        #pragma unroll
        for (int i = 0; i < 5; ++i) {
            u64 wa, wb;
            cld4(CBOUT + 4 * i, wa, wb);
            O[2 * i] = wa; O[2 * i + 1] = wb;
        }
        // a2 @ G via CONSTANT (cp dies progressively)
        #pragma unroll
        for (int k = 0; k < KK; ++k) {
            float av = cp[k] * g;
            u64 a = pack2(av, av);
            #pragma unroll
            for (int i = 0; i < 5; ++i) {
                u64 wa, wb;
                cld4(CSG + k * KP + 4 * i, wa, wb);
                O[2 * i]     = ffma2(wa, a, O[2 * i]);
                O[2 * i + 1] = ffma2(wb, a, O[2 * i + 1]);
            }
        }
        // rank-4 update via CONSTANT
        {
            float cr[4] = { vf * s2 * s0, vf * s2 * s1, vf * s2 * s2v, vf };
            #pragma unroll
            for (int j = 0; j < 4; ++j) {
                u64 a = pack2(cr[j], cr[j]);
                #pragma unroll
                for (int i = 0; i < 5; ++i) {
                    u64 wa, wb;
                    cld4(CSP + j * KP + 4 * i, wa, wb);
                    O[2 * i]     = ffma2(wa, a, O[2 * i]);
                    O[2 * i + 1] = ffma2(wb, a, O[2 * i + 1]);
                }
            }
        }
        // f @ WT1 via SMEM (broadcast LDS.128), f re-read from own smem row
        #pragma unroll
        for (int d = 0; d < 32; ++d) {
            float fd = sF[t * 33 + d];
            u64 fd2 = pack2(fd, fd);
            const ulonglong2* r = reinterpret_cast<const ulonglong2*>(sW + GWT1 + d * KP);
            #pragma unroll
            for (int q = 0; q < 5; ++q) {
                ulonglong2 ww = r[q];
                O[2 * q]     = ffma2(ww.x, fd2, O[2 * q]);
                O[2 * q + 1] = ffma2(ww.y, fd2, O[2 * q + 1]);
            }
        }

        // ---- write output to own smem row ----
        #pragma unroll
        for (int i = 0; i < 10; ++i) {
            float x, y;
            unpack2(O[i], x, y);
            if (2 * i < KK)     sCP[t * KK + 2 * i]     = x;
            if (2 * i + 1 < KK) sCP[t * KK + 2 * i + 1] = y;
        }
    }
    __syncthreads();

    // ---- coalesced stage-out ----
    if (full) {
        float* og = out + (size_t)nb * (128 * KK);
        #pragma unroll
        for (int i = 0; i < KK; ++i) {
            int j = t + 128 * i;
            og[j] = sCP[j];
        }
    } else {
        const size_t baseE = (size_t)nb * (128 * KK);
        const size_t totE = (size_t)N * KK;
        #pragma unroll
        for (int i = 0; i < KK; ++i) {
            size_t gidx = baseE + t + 128 * i;
            if (gidx < totE) out[gidx] = sCP[t + 128 * i];
        }
    }
}

// ============================================================================
extern "C" void kernel_launch(void* const* d_in, const int* in_sizes, int n_in,
                              void* d_out, int out_size)
{
    const float* feat      = (const float*)d_in[0];
    const float* sflow     = (const float*)d_in[1];
    const float* cpred     = (const float*)d_in[2];
    const float* z         = (const float*)d_in[3];
    const float* select_w1 = (const float*)d_in[4];
    const float* bn_gamma  = (const float*)d_in[5];
    const float* bn_beta   = (const float*)d_in[6];
    const float* bn_mean   = (const float*)d_in[7];
    const float* bn_var    = (const float*)d_in[8];
    const float* select_w2 = (const float*)d_in[9];
    const float* select_b2 = (const float*)d_in[10];
    const float* wq        = (const float*)d_in[11];
    const float* bq        = (const float*)d_in[12];
    const float* wk        = (const float*)d_in[13];
    const float* bk        = (const float*)d_in[14];
    const float* wv        = (const float*)d_in[15];
    const float* bv        = (const float*)d_in[16];
    const float* wo        = (const float*)d_in[17];
    const float* bo        = (const float*)d_in[18];
    const float* wt        = (const float*)d_in[19];
    const float* bt        = (const float*)d_in[20];
    const float* w_out     = (const float*)d_in[21];
    const float* b_out     = (const float*)d_in[22];
    const float* w_gen     = (const float*)d_in[23];
    const float* b_gen     = (const float*)d_in[24];
    float* out = (float*)d_out;

    const int N = in_sizes[0] / 32;

    setup_kernel<<<1, 1024>>>(z, select_w1, bn_gamma, bn_beta, bn_mean, bn_var,
                              select_w2, select_b2, wq, bq, wk, bk, wv, bv,
                              wo, bo, wt, bt, w_out, b_out, w_gen, b_gen);

    void* cw_src = nullptr;
    cudaGetSymbolAddress(&cw_src, g_cw);
    cudaMemcpyToSymbolAsync(c_w, cw_src, CSZ * sizeof(float), 0,
                            cudaMemcpyDeviceToDevice, 0);

    refine_kernel<<<(N + 127) / 128, 128>>>(feat, sflow, cpred, out, N);
}

// round 15
// speedup vs baseline: 1.1024x; 1.1024x over previous
#include <cuda_runtime.h>
#include <math.h>

typedef unsigned long long u64;

#define KK 19
#define KP 20

// ---- constant-bank layout (floats) ----
#define CW1   0      // 1024 [d*32+c]  select_w1 * bn_scale
#define CM2   1024   // 128  [d*4+j]   rsC*wq@[sK0,sK1,sK2,bk]
#define CSP   1152   // 80   [j*20+k]  rows 0..2: sV_j@Wo2 ; row 3: bv@Wo2 + bo@WoT2
#define CSC2  1232   // 4    cM2
#define CB1F  1236   // 32   folded BN bias
#define CW2   1268   // 32   select_w2
#define CB2   1300   // 1 (+3 pad)
#define CSG   1304   // 400  [k'*20+k] G = BV@Wo2
#define CSC1  1704   // 20   cM1 (pad k=19 -> 0)
#define CBOUT 1724   // 20   b_out + bt@w_out (pad k=19 -> 0)
#define CSZ   1744

// ---- global weight buffer (smem-side): M1 then WT1 ----
#define GM1   0      // 640 [d*20+k] M1 = rsC*wq@BK^T
#define GWT1  640    // 640 [d*20+k] WT1 = wt[:32]@w_out
#define BUF2_SZ 1280

__constant__ __align__(16) float c_w[CSZ];
__device__ __align__(16) float g_cw[CSZ];
__device__ __align__(16) float g_buf[BUF2_SZ];

__device__ __forceinline__ u64 ffma2(u64 a, u64 b, u64 c) {
    u64 d; asm("fma.rn.f32x2 %0, %1, %2, %3;" : "=l"(d) : "l"(a), "l"(b), "l"(c)); return d;
}
__device__ __forceinline__ u64 pack2(float x, float y) {
    u64 r; asm("mov.b64 %0, {%1, %2};" : "=l"(r) : "f"(x), "f"(y)); return r;
}
__device__ __forceinline__ void unpack2(u64 v, float& x, float& y) {
    asm("mov.b64 {%0, %1}, %2;" : "=f"(x), "=f"(y) : "l"(v));
}
__device__ __forceinline__ void cld4(int idx, u64& a, u64& b) {
    float4 v = *reinterpret_cast<const float4*>(&c_w[idx]);
    a = pack2(v.x, v.y); b = pack2(v.z, v.w);
}
__device__ __forceinline__ u64 cld2(int idx) {
    float2 v = *reinterpret_cast<const float2*>(&c_w[idx]);
    return pack2(v.x, v.y);
}

// ============================================================================
// Setup kernel: fold all weights. 1 block, 1024 threads. (verified R11)
// ============================================================================
__global__ void setup_kernel(
    const float* __restrict__ z, const float* __restrict__ select_w1,
    const float* __restrict__ bn_gamma, const float* __restrict__ bn_beta,
    const float* __restrict__ bn_mean, const float* __restrict__ bn_var,
    const float* __restrict__ select_w2, const float* __restrict__ select_b2,
    const float* __restrict__ wq, const float* __restrict__ bq,
    const float* __restrict__ wk, const float* __restrict__ bk,
    const float* __restrict__ wv, const float* __restrict__ bv,
    const float* __restrict__ wo, const float* __restrict__ bo,
    const float* __restrict__ wt, const float* __restrict__ bt,
    const float* __restrict__ w_out, const float* __restrict__ b_out,
    const float* __restrict__ w_gen, const float* __restrict__ b_gen)
{
    __shared__ float s_zw[32];
    __shared__ float s_sK[96], s_sV[96];
    __shared__ float s_WoT2[640], s_Wo2[640];
    __shared__ float s_base[608];
    __shared__ float s_BK[608], s_BV[608];
    __shared__ float s_wq[1024], s_wk[1024], s_wv[1024], s_wo[1024];
    __shared__ float s_wt[2048], s_wout[608], s_wgen[1216];
    const int t = threadIdx.x;
    const float rsC = 0.17677669529663687f;

    // ---- burst prefetch (independent LDGs, MLP-overlapped) ----
    s_wq[t] = wq[t];
    s_wk[t] = wk[t];
    s_wv[t] = wv[t];
    s_wo[t] = wo[t];
    s_wt[t] = wt[t];
    s_wt[1024 + t] = wt[1024 + t];
    if (t < 608)  s_wout[t] = w_out[t];
    s_wgen[t] = (t < 1216) ? w_gen[t] : 0.f;
    if (t < 192)  s_wgen[1024 + t] = w_gen[1024 + t];

    {
        int c = t & 31;
        float sc = bn_gamma[c] * rsqrtf(bn_var[c] + 1e-4f);
        g_cw[CW1 + t] = select_w1[t] * sc;
    }
    if (t < 32) {
        float sc = bn_gamma[t] * rsqrtf(bn_var[t] + 1e-4f);
        g_cw[CB1F + t] = bn_beta[t] - bn_mean[t] * sc;
        g_cw[CW2 + t]  = select_w2[t];
    }
    if (t == 32) g_cw[CB2] = select_b2[0];
    __syncthreads();

    // -------- Stage A --------
    if (t < 32) {
        float acc = b_gen[t];
        #pragma unroll
        for (int i = 0; i < 16; ++i) acc += z[i] * s_wgen[i * 32 + t];
        s_zw[t] = acc;
    }
    if (t < 96) {
        int j = t / 32, c = t % 32;
        float aK = 0.f, aV = 0.f;
        #pragma unroll
        for (int d = 0; d < 32; ++d) {
            float w = s_wgen[(35 + j) * 32 + d];
            aK += w * s_wk[d * 32 + c];
            aV += w * s_wv[d * 32 + c];
        }
        s_sK[t] = aK; s_sV[t] = aV;
    }
    if (t < 640) {
        int d = t / KP, k = t % KP;
        float a1 = 0.f, a2w = 0.f;
        if (k < KK) {
            #pragma unroll
            for (int e = 0; e < 32; ++e) {
                a1  += s_wt[d * 32 + e]        * s_wout[e * KK + k];
                a2w += s_wt[(32 + d) * 32 + e] * s_wout[e * KK + k];
            }
        }
        g_buf[GWT1 + d * KP + k] = a1;
        s_WoT2[t] = a2w;
    }
    if (t >= 640 && t < 660) {
        int k = t - 640; float a = 0.f;
        if (k < KK) {
            a = b_out[k];
            #pragma unroll
            for (int e = 0; e < 32; ++e) a += bt[e] * s_wout[e * KK + k];
        }
        g_cw[CBOUT + k] = a;
    }
    __syncthreads();

    // -------- Stage B --------
    if (t < 608)
        s_base[t] = s_zw[t & 31] + s_wgen[(16 + (t >> 5)) * 32 + (t & 31)];
    if (t < 640) {
        int c = t / KP, k = t % KP; float a = 0.f;
        if (k < KK) {
            #pragma unroll
            for (int d = 0; d < 32; ++d) a += s_wo[c * 32 + d] * s_WoT2[d * KP + k];
        }
        s_Wo2[t] = a;
    }
    __syncthreads();

    // -------- Stage C --------
    if (t < 608) {
        int k = t >> 5, c = t & 31;
        float ak = 0.f, av = 0.f;
        #pragma unroll
        for (int d = 0; d < 32; ++d) {
            float b = s_base[k * 32 + d];
            ak += b * s_wk[d * 32 + c];
            av += b * s_wv[d * 32 + c];
        }
        s_BK[t] = ak; s_BV[t] = av;
    }
    if (t >= 608 && t < 688) {
        int j = (t - 608) / KP, k = (t - 608) % KP;
        float a = 0.f;
        if (k < KK) {
            if (j < 3) {
                #pragma unroll
                for (int c = 0; c < 32; ++c) a += s_sV[j * 32 + c] * s_Wo2[c * KP + k];
            } else {
                #pragma unroll
                for (int c = 0; c < 32; ++c) a += bv[c] * s_Wo2[c * KP + k];
                #pragma unroll
                for (int d = 0; d < 32; ++d) a += bo[d] * s_WoT2[d * KP + k];
            }
        }
        g_cw[CSP + j * KP + k] = a;
    }
    __syncthreads();

    // -------- Stage D --------
    if (t < 640) {   // M1
        int d = t / KP, k = t % KP; float a = 0.f;
        if (k < KK) {
            #pragma unroll
            for (int c = 0; c < 32; ++c) a += s_wq[d * 32 + c] * s_BK[k * 32 + c];
        }
        g_buf[GM1 + d * KP + k] = a * rsC;
    } else if (t < 768) {   // M2
        int d = (t - 640) / 4, j = (t - 640) % 4; float a = 0.f;
        if (j < 3) {
            #pragma unroll
            for (int c = 0; c < 32; ++c) a += s_wq[d * 32 + c] * s_sK[j * 32 + c];
        } else {
            #pragma unroll
            for (int c = 0; c < 32; ++c) a += s_wq[d * 32 + c] * bk[c];
        }
        g_cw[CM2 + d * 4 + j] = a * rsC;
    } else if (t < 788) {   // cM1
        int k = t - 768; float a = 0.f;
        if (k < KK) {
            #pragma unroll
            for (int c = 0; c < 32; ++c) a += bq[c] * s_BK[k * 32 + c];
        }
        g_cw[CSC1 + k] = a * rsC;
    } else if (t < 792) {   // cM2
        int j = t - 788; float a = 0.f;
        if (j < 3) {
            #pragma unroll
            for (int c = 0; c < 32; ++c) a += bq[c] * s_sK[j * 32 + c];
        } else {
            #pragma unroll
            for (int c = 0; c < 32; ++c) a += bq[c] * bk[c];
        }
        g_cw[CSC2 + j] = a * rsC;
    } else {                // SG
        for (int u = t - 792; u < KK * KP; u += 232) {
            int kp = u / KP, k = u % KP; float a = 0.f;
            if (k < KK) {
                #pragma unroll
                for (int c = 0; c < 32; ++c) a += s_BV[kp * 32 + c] * s_Wo2[c * KP + k];
            }
            g_cw[CSG + kp * KP + k] = a;
        }
    }
}

// ============================================================================
// Attention-logit chunk: cols [C0, C0+4*NW). IN-PLACE: cp[k] <- exp(lg)*cp[k].
// ============================================================================
template<int C0, int NW>
__device__ __forceinline__ void t_chunk1(
    const float* sM1, const float* f, float* cp,
    float qsK, float qbk, float& Se, float& Sm)
{
    u64 T[2 * NW];
    #pragma unroll
    for (int i = 0; i < 2 * NW; ++i) T[i] = cld2(CSC1 + C0 + 2 * i);
    #pragma unroll
    for (int d = 0; d < 32; ++d) {
        const ulonglong2* r = reinterpret_cast<const ulonglong2*>(sM1 + d * KP + C0);
        u64 fd2 = pack2(f[d], f[d]);
        #pragma unroll
        for (int i = 0; i < NW; ++i) {
            ulonglong2 ww = r[i];
            T[2 * i]     = ffma2(ww.x, fd2, T[2 * i]);
            T[2 * i + 1] = ffma2(ww.y, fd2, T[2 * i + 1]);
        }
    }
    #pragma unroll
    for (int i = 0; i < 2 * NW; ++i) {
        const int k0 = C0 + 2 * i, k1 = k0 + 1;
        float tx, ty;
        unpack2(T[i], tx, ty);
        if (k0 < KK) { float el = __expf(fmaf(cp[k0], tx + qsK, qbk)); Se += el; cp[k0] *= el; Sm += cp[k0]; }
        if (k1 < KK) { float el = __expf(fmaf(cp[k1], ty + qsK, qbk)); Se += el; cp[k1] *= el; Sm += cp[k1]; }
    }
}

// ============================================================================
// Main kernel: 1 pt/thread; occ-7 locked; u-cols fused into selection half-0
// (same port, disjoint accumulators).
// ============================================================================
__global__ void __launch_bounds__(128, 7) refine_kernel(
    const float* __restrict__ feat,
    const float* __restrict__ sflow,
    const float* __restrict__ cpred,
    float* __restrict__ out,
    int N)
{
    __shared__ __align__(16) float sW[BUF2_SZ];   // M1 @0, WT1 @640
    __shared__ float sF[128 * 33];                 // feat rows, pad 33
    __shared__ float sCP[128 * KK];                // cpred rows / out rows
    const int t = threadIdx.x;
    const int nb = blockIdx.x;
    const bool full = ((nb + 1) * 128 <= N);

    // ---- weights (M1 + WT1) ----
    #pragma unroll
    for (int i = 0; i < 3; ++i) {
        int idx = t + 128 * i;
        if (idx < BUF2_SZ / 4)
            reinterpret_cast<float4*>(sW)[idx] = reinterpret_cast<const float4*>(g_buf)[idx];
    }

    // ---- staging (fast path: no bounds checks, 32-bit offsets) ----
    if (full) {
        const float4* fp4 = reinterpret_cast<const float4*>(feat) + (size_t)nb * 1024;
        #pragma unroll
        for (int i = 0; i < 8; ++i) {
            int l4 = t + 128 * i;
            float4 v = fp4[l4];
            int nl = l4 >> 3, d4 = l4 & 7;
            float* p = sF + nl * 33 + 4 * d4;
            p[0] = v.x; p[1] = v.y; p[2] = v.z; p[3] = v.w;
        }
        const float* cpg = cpred + (size_t)nb * (128 * KK);
        #pragma unroll
        for (int i = 0; i < KK; ++i) {
            int j = t + 128 * i;
            sCP[j] = cpg[j];
        }
    } else {
        const size_t base4 = (size_t)nb * 1024;
        const size_t tot4 = ((size_t)N * 32) >> 2;
        #pragma unroll
        for (int i = 0; i < 8; ++i) {
            size_t j4 = base4 + t + 128 * i;
            if (j4 < tot4) {
                float4 v = reinterpret_cast<const float4*>(feat)[j4];
                int l4 = t + 128 * i;
                int nl = l4 >> 3, d4 = l4 & 7;
                float* p = sF + nl * 33 + 4 * d4;
                p[0] = v.x; p[1] = v.y; p[2] = v.z; p[3] = v.w;
            }
        }
        const size_t baseE = (size_t)nb * (128 * KK);
        const size_t totE = (size_t)N * KK;
        #pragma unroll
        for (int i = 0; i < KK; ++i) {
            size_t gidx = baseE + t + 128 * i;
            if (gidx < totE) sCP[t + 128 * i] = cpred[gidx];
        }
    }
    __syncthreads();

    const int n = nb * 128 + t;
    if (n < N) {
        const float* sfp = sflow + (size_t)n * 3;
        const float s0 = sfp[0], s1 = sfp[1], s2v = sfp[2];

        // ---- f from own smem row ----
        float f[32];
        #pragma unroll
        for (int d = 0; d < 32; ++d) f[d] = sF[t * 33 + d];

        // ---- selection score + u-cols, both CONSTANT port ----
        float vf, qsK, qbk;
        {
            float slin = c_w[CB2];
            // half 0 fused with u-cols (disjoint accumulators, same port)
            {
                u64 h[8];
                #pragma unroll
                for (int i = 0; i < 8; ++i) h[i] = 0ull;
                u64 u0 = cld2(CSC2), u1 = cld2(CSC2 + 2);
                #pragma unroll
                for (int d = 0; d < 32; ++d) {
                    u64 fd2 = pack2(f[d], f[d]);
                    #pragma unroll
                    for (int i = 0; i < 4; ++i) {
                        u64 wa, wb;
                        cld4(CW1 + d * 32 + 4 * i, wa, wb);
                        h[2 * i]     = ffma2(wa, fd2, h[2 * i]);
                        h[2 * i + 1] = ffma2(wb, fd2, h[2 * i + 1]);
                    }
                    u64 ma, mb;
                    cld4(CM2 + d * 4, ma, mb);
                    u0 = ffma2(ma, fd2, u0);
                    u1 = ffma2(mb, fd2, u1);
                }
                #pragma unroll
                for (int i = 0; i < 8; ++i) {
                    const int c = 2 * i;
                    float x, y;
                    unpack2(h[i], x, y);
                    slin += fmaxf(x + c_w[CB1F + c], 0.f) * c_w[CW2 + c]
                          + fmaxf(y + c_w[CB1F + c + 1], 0.f) * c_w[CW2 + c + 1];
                }
                float a, b, c, d2;
                unpack2(u0, a, b); unpack2(u1, c, d2);
                qsK = fmaf(s0, a, fmaf(s1, b, s2v * c));
                qbk = d2;
            }
            // half 1
            {
                u64 h[8];
                #pragma unroll
                for (int i = 0; i < 8; ++i) h[i] = 0ull;
                #pragma unroll
                for (int d = 0; d < 32; ++d) {
                    u64 fd2 = pack2(f[d], f[d]);
                    #pragma unroll
                    for (int i = 0; i < 4; ++i) {
                        u64 wa, wb;
                        cld4(CW1 + d * 32 + 16 + 4 * i, wa, wb);
                        h[2 * i]     = ffma2(wa, fd2, h[2 * i]);
                        h[2 * i + 1] = ffma2(wb, fd2, h[2 * i + 1]);
                    }
                }
                #pragma unroll
                for (int i = 0; i < 8; ++i) {
                    const int c = 16 + 2 * i;
                    float x, y;
                    unpack2(h[i], x, y);
                    slin += fmaxf(x + c_w[CB1F + c], 0.f) * c_w[CW2 + c]
                          + fmaxf(y + c_w[CB1F + c + 1], 0.f) * c_w[CW2 + c + 1];
                }
            }
            const float thr = 1.3862943611198906f;   // ln(4): sigmoid(s)<0.8 <=> s<ln4
            bool tmask = (s0 != 0.f) || (s1 != 0.f) || (s2v != 0.f);
            vf = (slin < thr && tmask) ? 1.f : 0.f;
        }

        // ---- coarse_pred softmax (own row, stride-19 conflict-free) ----
        float cp[KK];
        {
            float S = 0.f;
            #pragma unroll
            for (int k = 0; k < KK; ++k) { cp[k] = __expf(sCP[t * KK + k]); S += cp[k]; }
            float inv = 1.f / S;
            #pragma unroll
            for (int k = 0; k < KK; ++k) cp[k] *= inv;
        }

        // ---- attention logits (smem M1 + const cM1), chunked ----
        float Se = 0.f, Sm = 0.f;
        t_chunk1<0, 2>(sW + GM1, f, cp, qsK, qbk, Se, Sm);
        t_chunk1<8, 2>(sW + GM1, f, cp, qsK, qbk, Se, Sm);
        t_chunk1<16, 1>(sW + GM1, f, cp, qsK, qbk, Se, Sm);
        // f register live range ends here

        const float inv = 1.f / Se;
        const float g = vf * inv;
        const float s2 = Sm * inv;

        // ================= PHASE B: output accumulation ==================
        u64 O[10];
        #pragma unroll
        for (int i = 0; i < 5; ++i) {
            u64 wa, wb;
            cld4(CBOUT + 4 * i, wa, wb);
            O[2 * i] = wa; O[2 * i + 1] = wb;
        }
        // a2 @ G via CONSTANT (cp dies progressively)
        #pragma unroll
        for (int k = 0; k < KK; ++k) {
            float av = cp[k] * g;
            u64 a = pack2(av, av);
            #pragma unroll
            for (int i = 0; i < 5; ++i) {
                u64 wa, wb;
                cld4(CSG + k * KP + 4 * i, wa, wb);
                O[2 * i]     = ffma2(wa, a, O[2 * i]);
                O[2 * i + 1] = ffma2(wb, a, O[2 * i + 1]);
            }
        }
        // rank-4 update via CONSTANT
        {
            float cr[4] = { vf * s2 * s0, vf * s2 * s1, vf * s2 * s2v, vf };
            #pragma unroll
            for (int j = 0; j < 4; ++j) {
                u64 a = pack2(cr[j], cr[j]);
                #pragma unroll
                for (int i = 0; i < 5; ++i) {
                    u64 wa, wb;
                    cld4(CSP + j * KP + 4 * i, wa, wb);
                    O[2 * i]     = ffma2(wa, a, O[2 * i]);
                    O[2 * i + 1] = ffma2(wb, a, O[2 * i + 1]);
                }
            }
        }
        // f @ WT1 via SMEM (broadcast LDS.128), f re-read from own smem row
        #pragma unroll
        for (int d = 0; d < 32; ++d) {
            float fd = sF[t * 33 + d];
            u64 fd2 = pack2(fd, fd);
            const ulonglong2* r = reinterpret_cast<const ulonglong2*>(sW + GWT1 + d * KP);
            #pragma unroll
            for (int q = 0; q < 5; ++q) {
                ulonglong2 ww = r[q];
                O[2 * q]     = ffma2(ww.x, fd2, O[2 * q]);
                O[2 * q + 1] = ffma2(ww.y, fd2, O[2 * q + 1]);
            }
        }

        // ---- write output to own smem row ----
        #pragma unroll
        for (int i = 0; i < 10; ++i) {
            float x, y;
            unpack2(O[i], x, y);
            if (2 * i < KK)     sCP[t * KK + 2 * i]     = x;
            if (2 * i + 1 < KK) sCP[t * KK + 2 * i + 1] = y;
        }
    }
    __syncthreads();

    // ---- coalesced stage-out ----
    if (full) {
        float* og = out + (size_t)nb * (128 * KK);
        #pragma unroll
        for (int i = 0; i < KK; ++i) {
            int j = t + 128 * i;
            og[j] = sCP[j];
        }
    } else {
        const size_t baseE = (size_t)nb * (128 * KK);
        const size_t totE = (size_t)N * KK;
        #pragma unroll
        for (int i = 0; i < KK; ++i) {
            size_t gidx = baseE + t + 128 * i;
            if (gidx < totE) out[gidx] = sCP[t + 128 * i];
        }
    }
}

// ============================================================================
extern "C" void kernel_launch(void* const* d_in, const int* in_sizes, int n_in,
                              void* d_out, int out_size)
{
    const float* feat      = (const float*)d_in[0];
    const float* sflow     = (const float*)d_in[1];
    const float* cpred     = (const float*)d_in[2];
    const float* z         = (const float*)d_in[3];
    const float* select_w1 = (const float*)d_in[4];
    const float* bn_gamma  = (const float*)d_in[5];
    const float* bn_beta   = (const float*)d_in[6];
    const float* bn_mean   = (const float*)d_in[7];
    const float* bn_var    = (const float*)d_in[8];
    const float* select_w2 = (const float*)d_in[9];
    const float* select_b2 = (const float*)d_in[10];
    const float* wq        = (const float*)d_in[11];
    const float* bq        = (const float*)d_in[12];
    const float* wk        = (const float*)d_in[13];
    const float* bk        = (const float*)d_in[14];
    const float* wv        = (const float*)d_in[15];
    const float* bv        = (const float*)d_in[16];
    const float* wo        = (const float*)d_in[17];
    const float* bo        = (const float*)d_in[18];
    const float* wt        = (const float*)d_in[19];
    const float* bt        = (const float*)d_in[20];
    const float* w_out     = (const float*)d_in[21];
    const float* b_out     = (const float*)d_in[22];
    const float* w_gen     = (const float*)d_in[23];
    const float* b_gen     = (const float*)d_in[24];
    float* out = (float*)d_out;

    const int N = in_sizes[0] / 32;

    setup_kernel<<<1, 1024>>>(z, select_w1, bn_gamma, bn_beta, bn_mean, bn_var,
                              select_w2, select_b2, wq, bq, wk, bk, wv, bv,
                              wo, bo, wt, bt, w_out, b_out, w_gen, b_gen);

    void* cw_src = nullptr;
    cudaGetSymbolAddress(&cw_src, g_cw);
    cudaMemcpyToSymbolAsync(c_w, cw_src, CSZ * sizeof(float), 0,
                            cudaMemcpyDeviceToDevice, 0);

    refine_kernel<<<(N + 127) / 128, 128>>>(feat, sflow, cpred, out, N);
}

// round 16
// speedup vs baseline: 1.1096x; 1.0065x over previous
#include <cuda_runtime.h>
#include <math.h>

typedef unsigned long long u64;

#define KK 19
#define KP 20

// ---- constant-bank layout (floats) ----
#define CW1   0      // 1024 [d*32+c]  select_w1 * bn_scale
#define CM2   1024   // 128  [d*4+j]   rsC*wq@[sK0,sK1,sK2,bk]
#define CSP   1152   // 80   [j*20+k]  rows 0..2: sV_j@Wo2 ; row 3: bv@Wo2 + bo@WoT2
#define CSC2  1232   // 4    cM2
#define CB1F  1236   // 32   folded BN bias
#define CW2   1268   // 32   select_w2
#define CB2   1300   // 1 (+3 pad)
#define CSG   1304   // 400  [k'*20+k] G = BV@Wo2
#define CSC1  1704   // 20   cM1 (pad k=19 -> 0)
#define CBOUT 1724   // 20   b_out + bt@w_out (pad k=19 -> 0)
#define CSZ   1744

// ---- global weight buffer (smem-side): M1 then WT1 ----
#define GM1   0      // 640 [d*20+k] M1 = rsC*wq@BK^T
#define GWT1  640    // 640 [d*20+k] WT1 = wt[:32]@w_out
#define BUF2_SZ 1280

__constant__ __align__(16) float c_w[CSZ];
__device__ __align__(16) float g_cw[CSZ];
__device__ __align__(16) float g_buf[BUF2_SZ];

__device__ __forceinline__ u64 ffma2(u64 a, u64 b, u64 c) {
    u64 d; asm("fma.rn.f32x2 %0, %1, %2, %3;" : "=l"(d) : "l"(a), "l"(b), "l"(c)); return d;
}
__device__ __forceinline__ u64 pack2(float x, float y) {
    u64 r; asm("mov.b64 %0, {%1, %2};" : "=l"(r) : "f"(x), "f"(y)); return r;
}
__device__ __forceinline__ void unpack2(u64 v, float& x, float& y) {
    asm("mov.b64 {%0, %1}, %2;" : "=f"(x), "=f"(y) : "l"(v));
}
__device__ __forceinline__ void cld4(int idx, u64& a, u64& b) {
    float4 v = *reinterpret_cast<const float4*>(&c_w[idx]);
    a = pack2(v.x, v.y); b = pack2(v.z, v.w);
}
__device__ __forceinline__ u64 cld2(int idx) {
    float2 v = *reinterpret_cast<const float2*>(&c_w[idx]);
    return pack2(v.x, v.y);
}

// ============================================================================
// Setup kernel: fold all weights. 1 block, 1024 threads. (verified R11-R15)
// ============================================================================
__global__ void setup_kernel(
    const float* __restrict__ z, const float* __restrict__ select_w1,
    const float* __restrict__ bn_gamma, const float* __restrict__ bn_beta,
    const float* __restrict__ bn_mean, const float* __restrict__ bn_var,
    const float* __restrict__ select_w2, const float* __restrict__ select_b2,
    const float* __restrict__ wq, const float* __restrict__ bq,
    const float* __restrict__ wk, const float* __restrict__ bk,
    const float* __restrict__ wv, const float* __restrict__ bv,
    const float* __restrict__ wo, const float* __restrict__ bo,
    const float* __restrict__ wt, const float* __restrict__ bt,
    const float* __restrict__ w_out, const float* __restrict__ b_out,
    const float* __restrict__ w_gen, const float* __restrict__ b_gen)
{
    __shared__ float s_zw[32];
    __shared__ float s_sK[96], s_sV[96];
    __shared__ float s_WoT2[640], s_Wo2[640];
    __shared__ float s_base[608];
    __shared__ float s_BK[608], s_BV[608];
    __shared__ float s_wq[1024], s_wk[1024], s_wv[1024], s_wo[1024];
    __shared__ float s_wt[2048], s_wout[608], s_wgen[1216];
    const int t = threadIdx.x;
    const float rsC = 0.17677669529663687f;

    // ---- burst prefetch (independent LDGs, MLP-overlapped) ----
    s_wq[t] = wq[t];
    s_wk[t] = wk[t];
    s_wv[t] = wv[t];
    s_wo[t] = wo[t];
    s_wt[t] = wt[t];
    s_wt[1024 + t] = wt[1024 + t];
    if (t < 608)  s_wout[t] = w_out[t];
    s_wgen[t] = (t < 1216) ? w_gen[t] : 0.f;
    if (t < 192)  s_wgen[1024 + t] = w_gen[1024 + t];

    {
        int c = t & 31;
        float sc = bn_gamma[c] * rsqrtf(bn_var[c] + 1e-4f);
        g_cw[CW1 + t] = select_w1[t] * sc;
    }
    if (t < 32) {
        float sc = bn_gamma[t] * rsqrtf(bn_var[t] + 1e-4f);
        g_cw[CB1F + t] = bn_beta[t] - bn_mean[t] * sc;
        g_cw[CW2 + t]  = select_w2[t];
    }
    if (t == 32) g_cw[CB2] = select_b2[0];
    __syncthreads();

    // -------- Stage A --------
    if (t < 32) {
        float acc = b_gen[t];
        #pragma unroll
        for (int i = 0; i < 16; ++i) acc += z[i] * s_wgen[i * 32 + t];
        s_zw[t] = acc;
    }
    if (t < 96) {
        int j = t / 32, c = t % 32;
        float aK = 0.f, aV = 0.f;
        #pragma unroll
        for (int d = 0; d < 32; ++d) {
            float w = s_wgen[(35 + j) * 32 + d];
            aK += w * s_wk[d * 32 + c];
            aV += w * s_wv[d * 32 + c];
        }
        s_sK[t] = aK; s_sV[t] = aV;
    }
    if (t < 640) {
        int d = t / KP, k = t % KP;
        float a1 = 0.f, a2w = 0.f;
        if (k < KK) {
            #pragma unroll
            for (int e = 0; e < 32; ++e) {
                a1  += s_wt[d * 32 + e]        * s_wout[e * KK + k];
                a2w += s_wt[(32 + d) * 32 + e] * s_wout[e * KK + k];
            }
        }
        g_buf[GWT1 + d * KP + k] = a1;
        s_WoT2[t] = a2w;
    }
    if (t >= 640 && t < 660) {
        int k = t - 640; float a = 0.f;
        if (k < KK) {
            a = b_out[k];
            #pragma unroll
            for (int e = 0; e < 32; ++e) a += bt[e] * s_wout[e * KK + k];
        }
        g_cw[CBOUT + k] = a;
    }
    __syncthreads();

    // -------- Stage B --------
    if (t < 608)
        s_base[t] = s_zw[t & 31] + s_wgen[(16 + (t >> 5)) * 32 + (t & 31)];
    if (t < 640) {
        int c = t / KP, k = t % KP; float a = 0.f;
        if (k < KK) {
            #pragma unroll
            for (int d = 0; d < 32; ++d) a += s_wo[c * 32 + d] * s_WoT2[d * KP + k];
        }
        s_Wo2[t] = a;
    }
    __syncthreads();

    // -------- Stage C --------
    if (t < 608) {
        int k = t >> 5, c = t & 31;
        float ak = 0.f, av = 0.f;
        #pragma unroll
        for (int d = 0; d < 32; ++d) {
            float b = s_base[k * 32 + d];
            ak += b * s_wk[d * 32 + c];
            av += b * s_wv[d * 32 + c];
        }
        s_BK[t] = ak; s_BV[t] = av;
    }
    if (t >= 608 && t < 688) {
        int j = (t - 608) / KP, k = (t - 608) % KP;
        float a = 0.f;
        if (k < KK) {
            if (j < 3) {
                #pragma unroll
                for (int c = 0; c < 32; ++c) a += s_sV[j * 32 + c] * s_Wo2[c * KP + k];
            } else {
                #pragma unroll
                for (int c = 0; c < 32; ++c) a += bv[c] * s_Wo2[c * KP + k];
                #pragma unroll
                for (int d = 0; d < 32; ++d) a += bo[d] * s_WoT2[d * KP + k];
            }
        }
        g_cw[CSP + j * KP + k] = a;
    }
    __syncthreads();

    // -------- Stage D --------
    if (t < 640) {   // M1
        int d = t / KP, k = t % KP; float a = 0.f;
        if (k < KK) {
            #pragma unroll
            for (int c = 0; c < 32; ++c) a += s_wq[d * 32 + c] * s_BK[k * 32 + c];
        }
        g_buf[GM1 + d * KP + k] = a * rsC;
    } else if (t < 768) {   // M2
        int d = (t - 640) / 4, j = (t - 640) % 4; float a = 0.f;
        if (j < 3) {
            #pragma unroll
            for (int c = 0; c < 32; ++c) a += s_wq[d * 32 + c] * s_sK[j * 32 + c];
        } else {
            #pragma unroll
            for (int c = 0; c < 32; ++c) a += s_wq[d * 32 + c] * bk[c];
        }
        g_cw[CM2 + d * 4 + j] = a * rsC;
    } else if (t < 788) {   // cM1
        int k = t - 768; float a = 0.f;
        if (k < KK) {
            #pragma unroll
            for (int c = 0; c < 32; ++c) a += bq[c] * s_BK[k * 32 + c];
        }
        g_cw[CSC1 + k] = a * rsC;
    } else if (t < 792) {   // cM2
        int j = t - 788; float a = 0.f;
        if (j < 3) {
            #pragma unroll
            for (int c = 0; c < 32; ++c) a += bq[c] * s_sK[j * 32 + c];
        } else {
            #pragma unroll
            for (int c = 0; c < 32; ++c) a += bq[c] * bk[c];
        }
        g_cw[CSC2 + j] = a * rsC;
    } else {                // SG
        for (int u = t - 792; u < KK * KP; u += 232) {
            int kp = u / KP, k = u % KP; float a = 0.f;
            if (k < KK) {
                #pragma unroll
                for (int c = 0; c < 32; ++c) a += s_BV[kp * 32 + c] * s_Wo2[c * KP + k];
            }
            g_cw[CSG + kp * KP + k] = a;
        }
    }
}

// ============================================================================
// Attention-logit chunk: cols [C0, C0+4*NW). IN-PLACE: cp[k] <- exp(lg)*cp[k].
// ============================================================================
template<int C0, int NW>
__device__ __forceinline__ void t_chunk1(
    const float* sM1, const float* f, float* cp,
    float qsK, float qbk, float& Se, float& Sm)
{
    u64 T[2 * NW];
    #pragma unroll
    for (int i = 0; i < 2 * NW; ++i) T[i] = cld2(CSC1 + C0 + 2 * i);
    #pragma unroll
    for (int d = 0; d < 32; ++d) {
        const ulonglong2* r = reinterpret_cast<const ulonglong2*>(sM1 + d * KP + C0);
        u64 fd2 = pack2(f[d], f[d]);
        #pragma unroll
        for (int i = 0; i < NW; ++i) {
            ulonglong2 ww = r[i];
            T[2 * i]     = ffma2(ww.x, fd2, T[2 * i]);
            T[2 * i + 1] = ffma2(ww.y, fd2, T[2 * i + 1]);
        }
    }
    #pragma unroll
    for (int i = 0; i < 2 * NW; ++i) {
        const int k0 = C0 + 2 * i, k1 = k0 + 1;
        float tx, ty;
        unpack2(T[i], tx, ty);
        if (k0 < KK) { float el = __expf(fmaf(cp[k0], tx + qsK, qbk)); Se += el; cp[k0] *= el; Sm += cp[k0]; }
        if (k1 < KK) { float el = __expf(fmaf(cp[k1], ty + qsK, qbk)); Se += el; cp[k1] *= el; Sm += cp[k1]; }
    }
}

// ============================================================================
// Main kernel: champion config; sflow hoisted pre-staging; fast reciprocals.
// ============================================================================
__global__ void __launch_bounds__(128, 7) refine_kernel(
    const float* __restrict__ feat,
    const float* __restrict__ sflow,
    const float* __restrict__ cpred,
    float* __restrict__ out,
    int N)
{
    __shared__ __align__(16) float sW[BUF2_SZ];   // M1 @0, WT1 @640
    __shared__ float sF[128 * 33];                 // feat rows, pad 33
    __shared__ float sCP[128 * KK];                // cpred rows / out rows
    const int t = threadIdx.x;
    const int nb = blockIdx.x;
    const bool full = ((nb + 1) * 128 <= N);
    const int n = nb * 128 + t;
    const bool live = (n < N);

    // ---- hoisted sflow loads: strided LDGs issue BEFORE the staging burst,
    //      their latency and L1 wavefronts overlap staging + barrier ----
    float s0 = 0.f, s1 = 0.f, s2v = 0.f;
    if (live) {
        const float* sfp = sflow + (size_t)n * 3;
        s0 = sfp[0]; s1 = sfp[1]; s2v = sfp[2];
    }

    // ---- weights (M1 + WT1) ----
    #pragma unroll
    for (int i = 0; i < 3; ++i) {
        int idx = t + 128 * i;
        if (idx < BUF2_SZ / 4)
            reinterpret_cast<float4*>(sW)[idx] = reinterpret_cast<const float4*>(g_buf)[idx];
    }

    // ---- staging (fast path: no bounds checks, 32-bit offsets) ----
    if (full) {
        const float4* fp4 = reinterpret_cast<const float4*>(feat) + (size_t)nb * 1024;
        #pragma unroll
        for (int i = 0; i < 8; ++i) {
            int l4 = t + 128 * i;
            float4 v = fp4[l4];
            int nl = l4 >> 3, d4 = l4 & 7;
            float* p = sF + nl * 33 + 4 * d4;
            p[0] = v.x; p[1] = v.y; p[2] = v.z; p[3] = v.w;
        }
        const float* cpg = cpred + (size_t)nb * (128 * KK);
        #pragma unroll
        for (int i = 0; i < KK; ++i) {
            int j = t + 128 * i;
            sCP[j] = cpg[j];
        }
    } else {
        const size_t base4 = (size_t)nb * 1024;
        const size_t tot4 = ((size_t)N * 32) >> 2;
        #pragma unroll
        for (int i = 0; i < 8; ++i) {
            size_t j4 = base4 + t + 128 * i;
            if (j4 < tot4) {
                float4 v = reinterpret_cast<const float4*>(feat)[j4];
                int l4 = t + 128 * i;
                int nl = l4 >> 3, d4 = l4 & 7;
                float* p = sF + nl * 33 + 4 * d4;
                p[0] = v.x; p[1] = v.y; p[2] = v.z; p[3] = v.w;
            }
        }
        const size_t baseE = (size_t)nb * (128 * KK);
        const size_t totE = (size_t)N * KK;
        #pragma unroll
        for (int i = 0; i < KK; ++i) {
            size_t gidx = baseE + t + 128 * i;
            if (gidx < totE) sCP[t + 128 * i] = cpred[gidx];
        }
    }
    __syncthreads();

    if (live) {
        // ---- f from own smem row ----
        float f[32];
        #pragma unroll
        for (int d = 0; d < 32; ++d) f[d] = sF[t * 33 + d];

        // ---- selection score + u-cols, both CONSTANT port ----
        float vf, qsK, qbk;
        {
            float slin = c_w[CB2];
            // half 0 fused with u-cols (disjoint accumulators, same port)
            {
                u64 h[8];
                #pragma unroll
                for (int i = 0; i < 8; ++i) h[i] = 0ull;
                u64 u0 = cld2(CSC2), u1 = cld2(CSC2 + 2);
                #pragma unroll
                for (int d = 0; d < 32; ++d) {
                    u64 fd2 = pack2(f[d], f[d]);
                    #pragma unroll
                    for (int i = 0; i < 4; ++i) {
                        u64 wa, wb;
                        cld4(CW1 + d * 32 + 4 * i, wa, wb);
                        h[2 * i]     = ffma2(wa, fd2, h[2 * i]);
                        h[2 * i + 1] = ffma2(wb, fd2, h[2 * i + 1]);
                    }
                    u64 ma, mb;
                    cld4(CM2 + d * 4, ma, mb);
                    u0 = ffma2(ma, fd2, u0);
                    u1 = ffma2(mb, fd2, u1);
                }
                #pragma unroll
                for (int i = 0; i < 8; ++i) {
                    const int c = 2 * i;
                    float x, y;
                    unpack2(h[i], x, y);
                    slin += fmaxf(x + c_w[CB1F + c], 0.f) * c_w[CW2 + c]
                          + fmaxf(y + c_w[CB1F + c + 1], 0.f) * c_w[CW2 + c + 1];
                }
                float a, b, c, d2;
                unpack2(u0, a, b); unpack2(u1, c, d2);
                qsK = fmaf(s0, a, fmaf(s1, b, s2v * c));
                qbk = d2;
            }
            // half 1
            {
                u64 h[8];
                #pragma unroll
                for (int i = 0; i < 8; ++i) h[i] = 0ull;
                #pragma unroll
                for (int d = 0; d < 32; ++d) {
                    u64 fd2 = pack2(f[d], f[d]);
                    #pragma unroll
                    for (int i = 0; i < 4; ++i) {
                        u64 wa, wb;
                        cld4(CW1 + d * 32 + 16 + 4 * i, wa, wb);
                        h[2 * i]     = ffma2(wa, fd2, h[2 * i]);
                        h[2 * i + 1] = ffma2(wb, fd2, h[2 * i + 1]);
                    }
                }
                #pragma unroll
                for (int i = 0; i < 8; ++i) {
                    const int c = 16 + 2 * i;
                    float x, y;
                    unpack2(h[i], x, y);
                    slin += fmaxf(x + c_w[CB1F + c], 0.f) * c_w[CW2 + c]
                          + fmaxf(y + c_w[CB1F + c + 1], 0.f) * c_w[CW2 + c + 1];
                }
            }
            const float thr = 1.3862943611198906f;   // ln(4): sigmoid(s)<0.8 <=> s<ln4
            bool tmask = (s0 != 0.f) || (s1 != 0.f) || (s2v != 0.f);
            vf = (slin < thr && tmask) ? 1.f : 0.f;
        }

        // ---- coarse_pred softmax (own row, stride-19 conflict-free) ----
        float cp[KK];
        {
            float S = 0.f;
            #pragma unroll
            for (int k = 0; k < KK; ++k) { cp[k] = __expf(sCP[t * KK + k]); S += cp[k]; }
            float inv = __fdividef(1.f, S);
            #pragma unroll
            for (int k = 0; k < KK; ++k) cp[k] *= inv;
        }

        // ---- attention logits (smem M1 + const cM1), chunked ----
        float Se = 0.f, Sm = 0.f;
        t_chunk1<0, 2>(sW + GM1, f, cp, qsK, qbk, Se, Sm);
        t_chunk1<8, 2>(sW + GM1, f, cp, qsK, qbk, Se, Sm);
        t_chunk1<16, 1>(sW + GM1, f, cp, qsK, qbk, Se, Sm);
        // f register live range ends here

        const float inv = __fdividef(1.f, Se);
        const float g = vf * inv;
        const float s2 = Sm * inv;

        // ================= PHASE B: output accumulation ==================
        u64 O[10];
        #pragma unroll
        for (int i = 0; i < 5; ++i) {
            u64 wa, wb;
            cld4(CBOUT + 4 * i, wa, wb);
            O[2 * i] = wa; O[2 * i + 1] = wb;
        }
        // a2 @ G via CONSTANT (cp dies progressively)
        #pragma unroll
        for (int k = 0; k < KK; ++k) {
            float av = cp[k] * g;
            u64 a = pack2(av, av);
            #pragma unroll
            for (int i = 0; i < 5; ++i) {
                u64 wa, wb;
                cld4(CSG + k * KP + 4 * i, wa, wb);
                O[2 * i]     = ffma2(wa, a, O[2 * i]);
                O[2 * i + 1] = ffma2(wb, a, O[2 * i + 1]);
            }
        }
        // rank-4 update via CONSTANT
        {
            float cr[4] = { vf * s2 * s0, vf * s2 * s1, vf * s2 * s2v, vf };
            #pragma unroll
            for (int j = 0; j < 4; ++j) {
                u64 a = pack2(cr[j], cr[j]);
                #pragma unroll
                for (int i = 0; i < 5; ++i) {
                    u64 wa, wb;
                    cld4(CSP + j * KP + 4 * i, wa, wb);
                    O[2 * i]     = ffma2(wa, a, O[2 * i]);
                    O[2 * i + 1] = ffma2(wb, a, O[2 * i + 1]);
                }
            }
        }
        // f @ WT1 via SMEM (broadcast LDS.128), f re-read from own smem row
        #pragma unroll
        for (int d = 0; d < 32; ++d) {
            float fd = sF[t * 33 + d];
            u64 fd2 = pack2(fd, fd);
            const ulonglong2* r = reinterpret_cast<const ulonglong2*>(sW + GWT1 + d * KP);
            #pragma unroll
            for (int q = 0; q < 5; ++q) {
                ulonglong2 ww = r[q];
                O[2 * q]     = ffma2(ww.x, fd2, O[2 * q]);
                O[2 * q + 1] = ffma2(ww.y, fd2, O[2 * q + 1]);
            }
        }

        // ---- write output to own smem row ----
        #pragma unroll
        for (int i = 0; i < 10; ++i) {
            float x, y;
            unpack2(O[i], x, y);
            if (2 * i < KK)     sCP[t * KK + 2 * i]     = x;
            if (2 * i + 1 < KK) sCP[t * KK + 2 * i + 1] = y;
        }
    }
    __syncthreads();

    // ---- coalesced stage-out ----
    if (full) {
        float* og = out + (size_t)nb * (128 * KK);
        #pragma unroll
        for (int i = 0; i < KK; ++i) {
            int j = t + 128 * i;
            og[j] = sCP[j];
        }
    } else {
        const size_t baseE = (size_t)nb * (128 * KK);
        const size_t totE = (size_t)N * KK;
        #pragma unroll
        for (int i = 0; i < KK; ++i) {
            size_t gidx = baseE + t + 128 * i;
            if (gidx < totE) out[gidx] = sCP[t + 128 * i];
        }
    }
}

// ============================================================================
extern "C" void kernel_launch(void* const* d_in, const int* in_sizes, int n_in,
                              void* d_out, int out_size)
{
    const float* feat      = (const float*)d_in[0];
    const float* sflow     = (const float*)d_in[1];
    const float* cpred     = (const float*)d_in[2];
    const float* z         = (const float*)d_in[3];
    const float* select_w1 = (const float*)d_in[4];
    const float* bn_gamma  = (const float*)d_in[5];
    const float* bn_beta   = (const float*)d_in[6];
    const float* bn_mean   = (const float*)d_in[7];
    const float* bn_var    = (const float*)d_in[8];
    const float* select_w2 = (const float*)d_in[9];
    const float* select_b2 = (const float*)d_in[10];
    const float* wq        = (const float*)d_in[11];
    const float* bq        = (const float*)d_in[12];
    const float* wk        = (const float*)d_in[13];
    const float* bk        = (const float*)d_in[14];
    const float* wv        = (const float*)d_in[15];
    const float* bv        = (const float*)d_in[16];
    const float* wo        = (const float*)d_in[17];
    const float* bo        = (const float*)d_in[18];
    const float* wt        = (const float*)d_in[19];
    const float* bt        = (const float*)d_in[20];
    const float* w_out     = (const float*)d_in[21];
    const float* b_out     = (const float*)d_in[22];
    const float* w_gen     = (const float*)d_in[23];
    const float* b_gen     = (const float*)d_in[24];
    float* out = (float*)d_out;

    const int N = in_sizes[0] / 32;

    setup_kernel<<<1, 1024>>>(z, select_w1, bn_gamma, bn_beta, bn_mean, bn_var,
                              select_w2, select_b2, wq, bq, wk, bk, wv, bv,
                              wo, bo, wt, bt, w_out, b_out, w_gen, b_gen);

    void* cw_src = nullptr;
    cudaGetSymbolAddress(&cw_src, g_cw);
    cudaMemcpyToSymbolAsync(c_w, cw_src, CSZ * sizeof(float), 0,
                            cudaMemcpyDeviceToDevice, 0);

    refine_kernel<<<(N + 127) / 128, 128>>>(feat, sflow, cpred, out, N);
}